// round 3
// baseline (speedup 1.0000x reference)
#include <cuda_runtime.h>
#include <cstdint>

// N=100000, E=1600000, D=8, K=1, C=32 (dims from in_sizes at runtime).
#define MAXN 100352
#define MAXE 1638400

__device__ __align__(16) float g_xg[MAXN * 32];     // x @ g
__device__ __align__(16) float g_rootb[MAXN * 32];  // root term (layer 1)
__device__ __align__(16) float g_rootb2[MAXN * 32]; // root term (layer 2)
__device__ __align__(16) float g_agg[MAXN * 32];    // scatter accumulator
__device__ float g_cnt[MAXN];                        // in-degree
__device__ float g_gau1[MAXE];                       // layer-1 gaussian weights
__device__ float g_gau2[MAXE];                       // layer-2 gaussian weights

// Precompute both layers' Gaussian edge weights in one coalesced pass.
// One thread per edge: 32B ea read (2x float4), two exp's, two 4B writes.
__global__ void __launch_bounds__(256) gau_k(
    const float4* __restrict__ ea,    // [E, 8] viewed as [E,2] float4
    const float* __restrict__ mu1, const float* __restrict__ s1,
    const float* __restrict__ mu2, const float* __restrict__ s2,
    float* __restrict__ gau1, float* __restrict__ gau2, int E) {
    int e = blockIdx.x * blockDim.x + threadIdx.x;
    if (e >= E) return;
    float4 a = ea[e * 2];
    float4 b = ea[e * 2 + 1];
    float v[8] = {a.x, a.y, a.z, a.w, b.x, b.y, b.z, b.w};
    float t1 = 0.f, t2 = 0.f;
#pragma unroll
    for (int d = 0; d < 8; d++) {
        float d1 = v[d] - __ldg(mu1 + d);
        float d2 = v[d] - __ldg(mu2 + d);
        t1 += (-0.5f * d1 * d1) / (1e-15f + __ldg(s1 + d) * __ldg(s1 + d));
        t2 += (-0.5f * d2 * d2) / (1e-15f + __ldg(s2 + d) * __ldg(s2 + d));
    }
    gau1[e] = __expf(t1);
    gau2[e] = __expf(t2);
}

// Register-weight GEMM; 128-row tile in shared. FUSE=true: input row =
// agg[row]/max(cnt,1) + rb_in[row], and agg is re-zeroed in place after
// reading (replaces the second memset).
template <bool FUSE>
__global__ void __launch_bounds__(256) gemm_k(
    float* __restrict__ xin,          // x (FUSE=false) or agg (FUSE=true)
    const float* __restrict__ cnt,
    const float* __restrict__ rb_in,
    const float* __restrict__ g,
    const float* __restrict__ root,
    const float* __restrict__ bias,
    float* __restrict__ xg,
    float* __restrict__ rb_out,
    int N) {
    __shared__ float sx[128][32];
    const int t = threadIdx.x;
    const int lane = t & 31;
    const int w = t >> 5;

    float wg[32], wr[32];
#pragma unroll
    for (int k = 0; k < 32; k++) {
        wg[k] = __ldg(g + k * 32 + lane);
        wr[k] = __ldg(root + k * 32 + lane);
    }
    const float bv = __ldg(bias + lane);

    const int base = blockIdx.x * 128;
    const int nrows = min(128, N - base);

    if (FUSE) {
        for (int i = t; i < nrows * 32; i += 256) {
            int r = i >> 5, c = i & 31;
            int row = base + r;
            float rinv = 1.0f / fmaxf(__ldg(cnt + row), 1.0f);
            size_t o = (size_t)row * 32 + c;
            sx[r][c] = xin[o] * rinv + rb_in[o];
            xin[o] = 0.0f;  // re-zero agg for the next edge pass
        }
    } else {
        for (int i = t; i < nrows * 32; i += 256)
            sx[i >> 5][i & 31] = xin[(size_t)base * 32 + i];
    }
    __syncthreads();

    for (int r = w; r < nrows; r += 8) {
        float a = 0.0f, b = bv;
#pragma unroll
        for (int k = 0; k < 32; k++) {
            float xv = sx[r][k];
            a = fmaf(xv, wg[k], a);
            b = fmaf(xv, wr[k], b);
        }
        size_t o = (size_t)(base + r) * 32 + lane;
        xg[o] = a;
        rb_out[o] = b;
    }
}

// Slim edge pass: 8 lanes per edge, lane l owns channels [4l,4l+4).
// Per lane: gau broadcast load, 2 index loads, one float4 gather, one v4 red.
__global__ void __launch_bounds__(256) edge_pass(
    const int* __restrict__ ei,      // [2, E]
    const float* __restrict__ gau,   // [E]
    const float4* __restrict__ xg,   // [N, 8] float4
    float* __restrict__ agg,         // [N, 32]
    float* __restrict__ cnt,         // [N]
    int E, int do_cnt) {
    long long idx = (long long)blockIdx.x * blockDim.x + threadIdx.x;
    int e = (int)(idx >> 3);
    int l = (int)(idx & 7);
    if (e >= E) return;

    float gv = __ldg(gau + e);
    int src = __ldg(ei + e);
    int dst = __ldg(ei + E + e);

    float4 v = xg[(size_t)src * 8 + l];
    v.x *= gv; v.y *= gv; v.z *= gv; v.w *= gv;

    float* p = agg + (size_t)dst * 32 + l * 4;
    asm volatile("red.global.add.v4.f32 [%0], {%1,%2,%3,%4};"
                 :: "l"(p), "f"(v.x), "f"(v.y), "f"(v.z), "f"(v.w)
                 : "memory");

    if (do_cnt && l == 0) atomicAdd(cnt + dst, 1.0f);
}

// out = agg / max(cnt,1) + rootb   (final layer only)
__global__ void __launch_bounds__(256) finalize4(
    const float4* __restrict__ agg,
    const float4* __restrict__ rootb,
    const float* __restrict__ cnt,
    float4* __restrict__ out,
    int N) {
    int i = blockIdx.x * blockDim.x + threadIdx.x;
    if (i >= N * 8) return;
    int n = i >> 3;
    float rinv = 1.0f / fmaxf(__ldg(cnt + n), 1.0f);
    float4 a = agg[i];
    float4 r = rootb[i];
    a.x = a.x * rinv + r.x;
    a.y = a.y * rinv + r.y;
    a.z = a.z * rinv + r.z;
    a.w = a.w * rinv + r.w;
    out[i] = a;
}

extern "C" void kernel_launch(void* const* d_in, const int* in_sizes, int n_in,
                              void* d_out, int out_size) {
    const int*   ei  = (const int*)d_in[0];
    const float* ew  = (const float*)d_in[1];
    const float* x   = (const float*)d_in[2];
    const float* g1  = (const float*)d_in[3];
    const float* mu1 = (const float*)d_in[4];
    const float* s1  = (const float*)d_in[5];
    const float* r1  = (const float*)d_in[6];
    const float* b1  = (const float*)d_in[7];
    const float* g2  = (const float*)d_in[8];
    const float* mu2 = (const float*)d_in[9];
    const float* s2  = (const float*)d_in[10];
    const float* r2  = (const float*)d_in[11];
    const float* b2  = (const float*)d_in[12];

    const int E = in_sizes[0] / 2;
    const int N = in_sizes[2] / 32;

    float *xg, *rootb, *rootb2, *agg, *cnt, *gau1, *gau2;
    cudaGetSymbolAddress((void**)&xg, g_xg);
    cudaGetSymbolAddress((void**)&rootb, g_rootb);
    cudaGetSymbolAddress((void**)&rootb2, g_rootb2);
    cudaGetSymbolAddress((void**)&agg, g_agg);
    cudaGetSymbolAddress((void**)&cnt, g_cnt);
    cudaGetSymbolAddress((void**)&gau1, g_gau1);
    cudaGetSymbolAddress((void**)&gau2, g_gau2);

    const int gemm_blocks = (N + 127) / 128;
    const int edge_blocks = (int)(((long long)E * 8 + 255) / 256);
    const int fin_blocks  = (N * 8 + 255) / 256;
    const int gau_blocks  = (E + 255) / 256;

    // precompute both layers' edge weights (independent of layer-1 result)
    gau_k<<<gau_blocks, 256>>>((const float4*)ew, mu1, s1, mu2, s2, gau1, gau2, E);

    // ---- layer 1 ----
    cudaMemsetAsync(agg, 0, (size_t)N * 32 * sizeof(float), 0);
    cudaMemsetAsync(cnt, 0, (size_t)N * sizeof(float), 0);
    gemm_k<false><<<gemm_blocks, 256>>>((float*)x, nullptr, nullptr, g1, r1, b1, xg, rootb, N);
    edge_pass<<<edge_blocks, 256>>>(ei, gau1, (const float4*)xg, agg, cnt, E, 1);

    // ---- layer 2 (finalize + agg re-zero fused into the GEMM) ----
    gemm_k<true><<<gemm_blocks, 256>>>(agg, cnt, rootb, g2, r2, b2, xg, rootb2, N);
    edge_pass<<<edge_blocks, 256>>>(ei, gau2, (const float4*)xg, agg, cnt, E, 0);
    finalize4<<<fin_blocks, 256>>>((const float4*)agg, (const float4*)rootb2, cnt, (float4*)d_out, N);
}

// round 4
// speedup vs baseline: 1.2492x; 1.2492x over previous
#include <cuda_runtime.h>
#include <cstdint>

// N=100000, E=1600000, D=8, K=1, C=32 (dims from in_sizes at runtime).
#define MAXN 100352
#define MAXE 1638400
#define SCAN_BLK 1024
#define MAX_SB 128   // max scan blocks (ceil(MAXN/1024) = 98)

__device__ __align__(16) float g_xg[MAXN * 32];      // x @ g
__device__ __align__(16) float g_rootb[MAXN * 32];   // root term (layer 1)
__device__ __align__(16) float g_rootb2[MAXN * 32];  // root term (layer 2)
__device__ __align__(16) float g_h[MAXN * 32];       // layer-1 output
__device__ __align__(16) float4 g_edges[MAXE];       // packed (src, gau1, gau2, -) sorted by dst
__device__ int g_cnt[MAXN];                           // in-degree histogram
__device__ int g_rowptr[MAXN + 1];                    // CSR row pointers (by dst)
__device__ int g_cursor[MAXN];                        // scatter cursors
__device__ int g_bsum[MAX_SB];                        // scan block sums

// ---------------- CSR build ----------------

__global__ void __launch_bounds__(256) hist_k(const int* __restrict__ ei, int* __restrict__ cnt, int E) {
    int e = blockIdx.x * blockDim.x + threadIdx.x;
    if (e < E) atomicAdd(cnt + __ldg(ei + E + e), 1);
}

// Per-block exclusive scan of 1024 counts; block totals to bsum.
__global__ void __launch_bounds__(SCAN_BLK) scan1_k(const int* __restrict__ cnt,
                                                    int* __restrict__ rowptr,
                                                    int* __restrict__ bsum, int N) {
    __shared__ int sh[SCAN_BLK];
    int t = threadIdx.x;
    int i = blockIdx.x * SCAN_BLK + t;
    int v = (i < N) ? cnt[i] : 0;
    sh[t] = v;
    __syncthreads();
    for (int off = 1; off < SCAN_BLK; off <<= 1) {
        int add = (t >= off) ? sh[t - off] : 0;
        __syncthreads();
        sh[t] += add;
        __syncthreads();
    }
    if (i < N) rowptr[i] = sh[t] - v;  // exclusive
    if (t == SCAN_BLK - 1) bsum[blockIdx.x] = sh[t];
}

// Exclusive scan of block sums (single block).
__global__ void __launch_bounds__(MAX_SB) scan2_k(int* __restrict__ bsum, int nb) {
    __shared__ int sh[MAX_SB];
    int t = threadIdx.x;
    int v = (t < nb) ? bsum[t] : 0;
    sh[t] = v;
    __syncthreads();
    for (int off = 1; off < MAX_SB; off <<= 1) {
        int add = (t >= off) ? sh[t - off] : 0;
        __syncthreads();
        sh[t] += add;
        __syncthreads();
    }
    if (t < nb) bsum[t] = sh[t] - v;
}

// Add block offsets; init cursors; set rowptr[N]=E.
__global__ void __launch_bounds__(SCAN_BLK) scan3_k(int* __restrict__ rowptr,
                                                    int* __restrict__ cursor,
                                                    const int* __restrict__ bsum,
                                                    int N, int E) {
    int i = blockIdx.x * SCAN_BLK + threadIdx.x;
    if (i < N) {
        int v = rowptr[i] + bsum[blockIdx.x];
        rowptr[i] = v;
        cursor[i] = v;
    }
    if (i == 0) rowptr[N] = E;
}

// Compute both layers' gaussian weights and scatter packed edge records
// (src, gau1, gau2) to their dst-sorted slot. One 16B write per edge.
__global__ void __launch_bounds__(256) gau_scatter_k(
    const int* __restrict__ ei,
    const float4* __restrict__ ea,    // [E,8] viewed as [E,2] float4
    const float* __restrict__ mu1, const float* __restrict__ s1,
    const float* __restrict__ mu2, const float* __restrict__ s2,
    int* __restrict__ cursor,
    float4* __restrict__ edges, int E) {
    int e = blockIdx.x * blockDim.x + threadIdx.x;
    if (e >= E) return;
    float4 a = ea[e * 2];
    float4 b = ea[e * 2 + 1];
    float v[8] = {a.x, a.y, a.z, a.w, b.x, b.y, b.z, b.w};
    float t1 = 0.f, t2 = 0.f;
#pragma unroll
    for (int d = 0; d < 8; d++) {
        float d1 = v[d] - __ldg(mu1 + d);
        float d2 = v[d] - __ldg(mu2 + d);
        t1 += (-0.5f * d1 * d1) / (1e-15f + __ldg(s1 + d) * __ldg(s1 + d));
        t2 += (-0.5f * d2 * d2) / (1e-15f + __ldg(s2 + d) * __ldg(s2 + d));
    }
    int src = __ldg(ei + e);
    int dst = __ldg(ei + E + e);
    int pos = atomicAdd(cursor + dst, 1);
    float4 rec;
    rec.x = __int_as_float(src);
    rec.y = __expf(t1);
    rec.z = __expf(t2);
    rec.w = 0.f;
    edges[pos] = rec;
}

// ---------------- GEMM (register weights) ----------------

__global__ void __launch_bounds__(256) gemm_k(
    const float* __restrict__ xin,
    const float* __restrict__ g,
    const float* __restrict__ root,
    const float* __restrict__ bias,
    float* __restrict__ xg,
    float* __restrict__ rb_out,
    int N) {
    __shared__ float sx[128][32];
    const int t = threadIdx.x;
    const int lane = t & 31;
    const int w = t >> 5;

    float wg[32], wr[32];
#pragma unroll
    for (int k = 0; k < 32; k++) {
        wg[k] = __ldg(g + k * 32 + lane);
        wr[k] = __ldg(root + k * 32 + lane);
    }
    const float bv = __ldg(bias + lane);

    const int base = blockIdx.x * 128;
    const int nrows = min(128, N - base);

    for (int i = t; i < nrows * 32; i += 256)
        sx[i >> 5][i & 31] = xin[(size_t)base * 32 + i];
    __syncthreads();

    for (int r = w; r < nrows; r += 8) {
        float a = 0.0f, b = bv;
#pragma unroll
        for (int k = 0; k < 32; k++) {
            float xv = sx[r][k];
            a = fmaf(xv, wg[k], a);
            b = fmaf(xv, wr[k], b);
        }
        size_t o = (size_t)(base + r) * 32 + lane;
        xg[o] = a;
        rb_out[o] = b;
    }
}

// ---------------- Pull aggregation (atomic-free) ----------------
// One warp per dst node; lane = channel. Per edge: broadcast float4 record +
// one coalesced 128B xg row. Epilogue: mean + root term, single write.
template <int LAYER>
__global__ void __launch_bounds__(256) pull_k(
    const int* __restrict__ rowptr,
    const float4* __restrict__ edges,
    const float* __restrict__ xg,     // [N,32]
    const float* __restrict__ rootb,  // [N,32]
    float* __restrict__ out,          // [N,32]
    int N) {
    int warp = (blockIdx.x * blockDim.x + threadIdx.x) >> 5;
    int lane = threadIdx.x & 31;
    if (warp >= N) return;

    int s = __ldg(rowptr + warp);
    int e = __ldg(rowptr + warp + 1);

    float acc = 0.f;
    int j = s;
    for (; j + 4 <= e; j += 4) {
        float4 p0 = edges[j], p1 = edges[j + 1], p2 = edges[j + 2], p3 = edges[j + 3];
        float x0 = xg[(size_t)__float_as_int(p0.x) * 32 + lane];
        float x1 = xg[(size_t)__float_as_int(p1.x) * 32 + lane];
        float x2 = xg[(size_t)__float_as_int(p2.x) * 32 + lane];
        float x3 = xg[(size_t)__float_as_int(p3.x) * 32 + lane];
        float g0 = (LAYER == 1) ? p0.y : p0.z;
        float g1 = (LAYER == 1) ? p1.y : p1.z;
        float g2 = (LAYER == 1) ? p2.y : p2.z;
        float g3 = (LAYER == 1) ? p3.y : p3.z;
        acc = fmaf(g0, x0, acc);
        acc = fmaf(g1, x1, acc);
        acc = fmaf(g2, x2, acc);
        acc = fmaf(g3, x3, acc);
    }
    for (; j < e; j++) {
        float4 p = edges[j];
        float xv = xg[(size_t)__float_as_int(p.x) * 32 + lane];
        acc = fmaf((LAYER == 1) ? p.y : p.z, xv, acc);
    }

    int deg = e - s;
    float rinv = (deg > 0) ? (1.0f / (float)deg) : 0.0f;
    size_t o = (size_t)warp * 32 + lane;
    out[o] = acc * rinv + rootb[o];
}

extern "C" void kernel_launch(void* const* d_in, const int* in_sizes, int n_in,
                              void* d_out, int out_size) {
    const int*   ei  = (const int*)d_in[0];
    const float* ew  = (const float*)d_in[1];
    const float* x   = (const float*)d_in[2];
    const float* g1  = (const float*)d_in[3];
    const float* mu1 = (const float*)d_in[4];
    const float* s1  = (const float*)d_in[5];
    const float* r1  = (const float*)d_in[6];
    const float* b1  = (const float*)d_in[7];
    const float* g2  = (const float*)d_in[8];
    const float* mu2 = (const float*)d_in[9];
    const float* s2  = (const float*)d_in[10];
    const float* r2  = (const float*)d_in[11];
    const float* b2  = (const float*)d_in[12];

    const int E = in_sizes[0] / 2;
    const int N = in_sizes[2] / 32;

    float *xg, *rootb, *rootb2, *h;
    float4* edges;
    int *cnt, *rowptr, *cursor, *bsum;
    cudaGetSymbolAddress((void**)&xg, g_xg);
    cudaGetSymbolAddress((void**)&rootb, g_rootb);
    cudaGetSymbolAddress((void**)&rootb2, g_rootb2);
    cudaGetSymbolAddress((void**)&h, g_h);
    cudaGetSymbolAddress((void**)&edges, g_edges);
    cudaGetSymbolAddress((void**)&cnt, g_cnt);
    cudaGetSymbolAddress((void**)&rowptr, g_rowptr);
    cudaGetSymbolAddress((void**)&cursor, g_cursor);
    cudaGetSymbolAddress((void**)&bsum, g_bsum);

    const int nb = (N + SCAN_BLK - 1) / SCAN_BLK;
    const int eb = (E + 255) / 256;
    const int gemm_blocks = (N + 127) / 128;
    const int pull_blocks = (N + 7) / 8;

    // ---- CSR build (shared by both layers) ----
    cudaMemsetAsync(cnt, 0, (size_t)N * sizeof(int), 0);
    hist_k<<<eb, 256>>>(ei, cnt, E);
    scan1_k<<<nb, SCAN_BLK>>>(cnt, rowptr, bsum, N);
    scan2_k<<<1, MAX_SB>>>(bsum, nb);
    scan3_k<<<nb, SCAN_BLK>>>(rowptr, cursor, bsum, N, E);
    gau_scatter_k<<<eb, 256>>>(ei, (const float4*)ew, mu1, s1, mu2, s2, cursor, edges, E);

    // ---- layer 1 ----
    gemm_k<<<gemm_blocks, 256>>>(x, g1, r1, b1, xg, rootb, N);
    pull_k<1><<<pull_blocks, 256>>>(rowptr, edges, xg, rootb, h, N);

    // ---- layer 2 ----
    gemm_k<<<gemm_blocks, 256>>>(h, g2, r2, b2, xg, rootb2, N);
    pull_k<2><<<pull_blocks, 256>>>(rowptr, edges, xg, rootb2, (float*)d_out, N);
}